// round 1
// baseline (speedup 1.0000x reference)
#include <cuda_runtime.h>
#include <math.h>
#include <float.h>

// ---------------- problem constants ----------------
#define TT     2048
#define HID    4096
#define NHEADS 32
#define NKVH   8
#define HDIM   128
#define QKVO   6144          // (32 + 2*8) * 128
#define RANK   256
#define NIM    512
#define NMEM   128
#define CACHE_ELEMS (4*64*NKVH*HDIM)   // 262144

// ---------------- scratch (device globals; no allocs allowed) ----------------
__device__ float g_qkv[TT * QKVO];        // 50.3 MB
__device__ float g_attn[TT * HID];        // 33.5 MB
__device__ float g_tmp_im[NIM * RANK];
__device__ float g_tmp_mem[NMEM * RANK];
__device__ float g_lora_im[NIM * QKVO];   // reused for wo-lora (needs NIM*HID < NIM*QKVO)
__device__ float g_lora_mem[NMEM * QKVO];

// =====================================================================
// SGEMM:  C[m,n] = sum_k A[row(m),k] * B[n,k]     (both row-major, K contiguous)
// BM=BN=128, BK=8, 256 threads, 8x8 microtile (split 4+4 to avoid bank conflicts)
// Requires M%128==0, N%128==0, K%8==0 (true for all shapes here).
// =====================================================================
__global__ __launch_bounds__(256) void sgemm_bt(
    const float* __restrict__ A, const float* __restrict__ B,
    float* __restrict__ C, int M, int N, int K,
    const int* __restrict__ gatherA)
{
    __shared__ float As[8][128];
    __shared__ float Bs[8][128];

    int tid = threadIdx.x;
    int bm = blockIdx.y, bn = blockIdx.x;
    int lr = tid >> 1;             // 0..127
    int lk = (tid & 1) << 2;       // 0 or 4

    int arow = bm * 128 + lr;
    if (gatherA) arow = gatherA[arow];
    const float* Ap = A + (size_t)arow * K + lk;
    const float* Bp = B + (size_t)(bn * 128 + lr) * K + lk;

    int tx = tid & 15, ty = tid >> 4;

    float acc[8][8];
#pragma unroll
    for (int i = 0; i < 8; i++)
#pragma unroll
        for (int j = 0; j < 8; j++) acc[i][j] = 0.f;

    for (int k0 = 0; k0 < K; k0 += 8) {
        float4 a4 = *(const float4*)(Ap + k0);
        float4 b4 = *(const float4*)(Bp + k0);
        __syncthreads();   // protect previous iteration's readers
        As[lk + 0][lr] = a4.x; As[lk + 1][lr] = a4.y;
        As[lk + 2][lr] = a4.z; As[lk + 3][lr] = a4.w;
        Bs[lk + 0][lr] = b4.x; Bs[lk + 1][lr] = b4.y;
        Bs[lk + 2][lr] = b4.z; Bs[lk + 3][lr] = b4.w;
        __syncthreads();

#pragma unroll
        for (int kk = 0; kk < 8; kk++) {
            float ar[8], br[8];
            *(float4*)(ar)     = *(const float4*)&As[kk][ty * 4];
            *(float4*)(ar + 4) = *(const float4*)&As[kk][ty * 4 + 64];
            *(float4*)(br)     = *(const float4*)&Bs[kk][tx * 4];
            *(float4*)(br + 4) = *(const float4*)&Bs[kk][tx * 4 + 64];
#pragma unroll
            for (int i = 0; i < 8; i++)
#pragma unroll
                for (int j = 0; j < 8; j++)
                    acc[i][j] = fmaf(ar[i], br[j], acc[i][j]);
        }
    }

#pragma unroll
    for (int i = 0; i < 8; i++) {
        int r = bm * 128 + ((i < 4) ? (ty * 4 + i) : (64 + ty * 4 + (i - 4)));
        float4 c0 = make_float4(acc[i][0], acc[i][1], acc[i][2], acc[i][3]);
        float4 c1 = make_float4(acc[i][4], acc[i][5], acc[i][6], acc[i][7]);
        *(float4*)&C[(size_t)r * N + bn * 128 + tx * 4]      = c0;
        *(float4*)&C[(size_t)r * N + bn * 128 + tx * 4 + 64] = c1;
    }
}

// =====================================================================
// Scatter-add: C[idx[row], :] += L[row, :]   (atomic: duplicates must accumulate)
// =====================================================================
__global__ void scatter_add_rows(float* __restrict__ C, const float* __restrict__ L,
                                 const int* __restrict__ idx, int N)
{
    int row = blockIdx.y;
    int col = blockIdx.x * 256 + threadIdx.x;
    int r = idx[row];
    atomicAdd(&C[(size_t)r * N + col], L[(size_t)row * N + col]);
}

// =====================================================================
// RoPE in place on q and k inside the qkv buffer. grid (T, 40), 64 threads.
// =====================================================================
__global__ void rope_qk_kernel(float* __restrict__ qkv,
                               const float* __restrict__ cosp,
                               const float* __restrict__ sinp)
{
    int t = blockIdx.x, h = blockIdx.y, d = threadIdx.x; // d < 64
    const float* c = cosp + (size_t)t * HDIM;
    const float* s = sinp + (size_t)t * HDIM;
    float* base;
    if (h < NHEADS) base = qkv + (size_t)t * QKVO + (size_t)((h >> 2) * 6 + (h & 3)) * HDIM;
    else            base = qkv + (size_t)t * QKVO + (size_t)((h - NHEADS) * 6 + 4) * HDIM;
    float x1 = base[d], x2 = base[d + 64];
    base[d]      = x1 * c[d]      - x2 * s[d];
    base[d + 64] = x2 * c[d + 64] + x1 * s[d + 64];
}

// =====================================================================
// KV-cache fill from RAW (pre-RoPE) k/v, with beacon RoPE on k.
// grid 128 blocks, block (64, 8)
// =====================================================================
__global__ void fill_cache_kernel(const float* __restrict__ qkv,
                                  const int* __restrict__ mem_idx,
                                  const int* __restrict__ blkoff,
                                  const float* __restrict__ bcos,
                                  const float* __restrict__ bsin,
                                  float* __restrict__ kc, float* __restrict__ vc)
{
    int m = blockIdx.x;          // 0..127
    int h = threadIdx.y;         // 0..7
    int d = threadIdx.x;         // 0..63
    int tok = mem_idx[m];
    int blk = blkoff[m >> 6];
    int off = m & 63;
    const float* kb = qkv + (size_t)tok * QKVO + (size_t)(h * 6 + 4) * HDIM;
    const float* vb = qkv + (size_t)tok * QKVO + (size_t)(h * 6 + 5) * HDIM;
    size_t dsti = (((size_t)(blk * 64 + off)) * NKVH + h) * HDIM;
    const float* c = bcos + (size_t)m * HDIM;
    const float* s = bsin + (size_t)m * HDIM;
    float x1 = kb[d], x2 = kb[d + 64];
    kc[dsti + d]      = x1 * c[d]      - x2 * s[d];
    kc[dsti + d + 64] = x2 * c[d + 64] + x1 * s[d + 64];
    vc[dsti + d]      = vb[d];
    vc[dsti + d + 64] = vb[d + 64];
}

// =====================================================================
// Flash attention (fp32), causal, GQA 4:1.
// grid (T/64 q-blocks, 32 heads), 256 threads, dynamic smem ~117 KB.
// =====================================================================
#define FA_SMEM ((3 * 64 * 132 + 64 * 68 + 3 * 64) * 4)

__global__ __launch_bounds__(256) void flash_attn_kernel(
    const float* __restrict__ qkv, float* __restrict__ outp)
{
    extern __shared__ float sm[];
    float* Qs    = sm;                       // 64 x 132
    float* Ks    = Qs + 64 * 132;
    float* Vs    = Ks + 64 * 132;
    float* Ps    = Vs + 64 * 132;            // 64 x 68
    float* m_run = Ps + 64 * 68;             // 64
    float* l_run = m_run + 64;
    float* fac   = l_run + 64;

    int tid = threadIdx.x;
    int qb = blockIdx.x, h = blockIdx.y;
    int kv = h >> 2, g = h & 3;
    int qoff = (kv * 6 + g) * HDIM;
    int koff = (kv * 6 + 4) * HDIM;
    int voff = (kv * 6 + 5) * HDIM;

#pragma unroll
    for (int ii = 0; ii < 8; ii++) {
        int idx = tid + 256 * ii;
        int r = idx >> 5, c4 = (idx & 31) << 2;
        float4 v = *(const float4*)(qkv + (size_t)(qb * 64 + r) * QKVO + qoff + c4);
        *(float4*)&Qs[r * 132 + c4] = v;
    }
    if (tid < 64) { m_run[tid] = -FLT_MAX; l_run[tid] = 0.f; }
    float O[32];
#pragma unroll
    for (int i = 0; i < 32; i++) O[i] = 0.f;
    __syncthreads();

    int rg   = tid >> 4;    // S-phase row group (4 rows)
    int lk16 = tid & 15;    // lane within row group
    int qi_o = tid >> 2;    // O-phase row
    int q4   = tid & 3;

    const float scale = 0.08838834764831845f; // 1/sqrt(128)

    for (int kb = 0; kb <= qb; kb++) {
#pragma unroll
        for (int ii = 0; ii < 8; ii++) {
            int idx = tid + 256 * ii;
            int r = idx >> 5, c4 = (idx & 31) << 2;
            const float* src = qkv + (size_t)(kb * 64 + r) * QKVO;
            *(float4*)&Ks[r * 132 + c4] = *(const float4*)(src + koff + c4);
            *(float4*)&Vs[r * 132 + c4] = *(const float4*)(src + voff + c4);
        }
        __syncthreads();

        float S[4][4];
#pragma unroll
        for (int i = 0; i < 4; i++)
#pragma unroll
            for (int j = 0; j < 4; j++) S[i][j] = 0.f;

#pragma unroll 4
        for (int d4 = 0; d4 < 32; d4++) {
            float4 qv[4], kk4[4];
#pragma unroll
            for (int i = 0; i < 4; i++)
                qv[i] = *(const float4*)&Qs[(rg * 4 + i) * 132 + d4 * 4];
#pragma unroll
            for (int j = 0; j < 4; j++)
                kk4[j] = *(const float4*)&Ks[(lk16 + 16 * j) * 132 + d4 * 4];
#pragma unroll
            for (int i = 0; i < 4; i++)
#pragma unroll
                for (int j = 0; j < 4; j++)
                    S[i][j] += qv[i].x * kk4[j].x + qv[i].y * kk4[j].y
                             + qv[i].z * kk4[j].z + qv[i].w * kk4[j].w;
        }

        int qg0 = qb * 64 + rg * 4;
        int kg0 = kb * 64 + lk16;
        float rmax[4];
#pragma unroll
        for (int i = 0; i < 4; i++) {
            rmax[i] = -FLT_MAX;
#pragma unroll
            for (int j = 0; j < 4; j++) {
                int kg = kg0 + 16 * j;
                S[i][j] = (kg <= qg0 + i) ? S[i][j] * scale : -FLT_MAX;
                rmax[i] = fmaxf(rmax[i], S[i][j]);
            }
        }
#pragma unroll
        for (int mm = 1; mm < 16; mm <<= 1)
#pragma unroll
            for (int i = 0; i < 4; i++)
                rmax[i] = fmaxf(rmax[i], __shfl_xor_sync(0xffffffffu, rmax[i], mm));

        if (lk16 == 0) {
#pragma unroll
            for (int i = 0; i < 4; i++) {
                int qi = rg * 4 + i;
                float mo = m_run[qi];
                float mn = fmaxf(mo, rmax[i]);
                m_run[qi] = mn;
                fac[qi] = __expf(mo - mn);
            }
        }
        __syncwarp();

        float rsum[4];
#pragma unroll
        for (int i = 0; i < 4; i++) {
            float mn = m_run[rg * 4 + i];
            rsum[i] = 0.f;
#pragma unroll
            for (int j = 0; j < 4; j++) {
                float p = __expf(S[i][j] - mn);
                rsum[i] += p;
                Ps[(rg * 4 + i) * 68 + lk16 + 16 * j] = p;
            }
        }
#pragma unroll
        for (int mm = 1; mm < 16; mm <<= 1)
#pragma unroll
            for (int i = 0; i < 4; i++)
                rsum[i] += __shfl_xor_sync(0xffffffffu, rsum[i], mm);
        if (lk16 == 0) {
#pragma unroll
            for (int i = 0; i < 4; i++) {
                int qi = rg * 4 + i;
                l_run[qi] = l_run[qi] * fac[qi] + rsum[i];
            }
        }
        __syncthreads();

        // O phase
        float f = fac[qi_o];
#pragma unroll
        for (int i = 0; i < 32; i++) O[i] *= f;
#pragma unroll 8
        for (int j = 0; j < 64; j++) {
            float p = Ps[qi_o * 68 + j];
#pragma unroll
            for (int cc = 0; cc < 8; cc++) {
                float4 vv = *(const float4*)&Vs[j * 132 + q4 * 4 + 16 * cc];
                O[cc * 4 + 0] = fmaf(p, vv.x, O[cc * 4 + 0]);
                O[cc * 4 + 1] = fmaf(p, vv.y, O[cc * 4 + 1]);
                O[cc * 4 + 2] = fmaf(p, vv.z, O[cc * 4 + 2]);
                O[cc * 4 + 3] = fmaf(p, vv.w, O[cc * 4 + 3]);
            }
        }
        __syncthreads();
    }

    float inv = 1.f / l_run[qi_o];
    size_t obase = (size_t)(qb * 64 + qi_o) * HID + (size_t)h * HDIM;
#pragma unroll
    for (int cc = 0; cc < 8; cc++) {
        float4 vv = make_float4(O[cc * 4 + 0] * inv, O[cc * 4 + 1] * inv,
                                O[cc * 4 + 2] * inv, O[cc * 4 + 3] * inv);
        *(float4*)&outp[obase + q4 * 4 + 16 * cc] = vv;
    }
}

// =====================================================================
// Host orchestration
// =====================================================================
extern "C" void kernel_launch(void* const* d_in, const int* in_sizes, int n_in,
                              void* d_out, int out_size)
{
    const float* hs     = (const float*)d_in[0];
    const float* cosp   = (const float*)d_in[1];
    const float* sinp   = (const float*)d_in[2];
    const float* bcos   = (const float*)d_in[3];
    const float* bsin   = (const float*)d_in[4];
    const int*   memidx = (const int*)d_in[5];
    const int*   imidx  = (const int*)d_in[6];
    const float* kc_in  = (const float*)d_in[7];
    const float* vc_in  = (const float*)d_in[8];
    const int*   blkoff = (const int*)d_in[9];
    const float* wqkv_w = (const float*)d_in[10];
    const float* wqkv_A = (const float*)d_in[11];
    const float* wqkv_B = (const float*)d_in[12];
    const float* wqkv_MA= (const float*)d_in[13];
    const float* wqkv_MB= (const float*)d_in[14];
    const float* wo_w   = (const float*)d_in[15];
    const float* wo_A   = (const float*)d_in[16];
    const float* wo_B   = (const float*)d_in[17];
    const float* wo_MA  = (const float*)d_in[18];
    const float* wo_MB  = (const float*)d_in[19];

    float* outp   = (float*)d_out;
    float* kc_out = outp + (size_t)TT * HID;
    float* vc_out = kc_out + CACHE_ELEMS;

    float *qkv, *attn, *tmp_im, *tmp_mem, *lora_im, *lora_mem;
    cudaGetSymbolAddress((void**)&qkv,      g_qkv);
    cudaGetSymbolAddress((void**)&attn,     g_attn);
    cudaGetSymbolAddress((void**)&tmp_im,   g_tmp_im);
    cudaGetSymbolAddress((void**)&tmp_mem,  g_tmp_mem);
    cudaGetSymbolAddress((void**)&lora_im,  g_lora_im);
    cudaGetSymbolAddress((void**)&lora_mem, g_lora_mem);

    // ---- QKV projection + PLoRA ----
    sgemm_bt<<<dim3(QKVO / 128, TT / 128), 256>>>(hs, wqkv_w, qkv, TT, QKVO, HID, nullptr);
    sgemm_bt<<<dim3(RANK / 128, NIM / 128), 256>>>(hs, wqkv_A, tmp_im, NIM, RANK, HID, imidx);
    sgemm_bt<<<dim3(RANK / 128, NMEM / 128), 256>>>(hs, wqkv_MA, tmp_mem, NMEM, RANK, HID, memidx);
    sgemm_bt<<<dim3(QKVO / 128, NIM / 128), 256>>>(tmp_im, wqkv_B, lora_im, NIM, QKVO, RANK, nullptr);
    sgemm_bt<<<dim3(QKVO / 128, NMEM / 128), 256>>>(tmp_mem, wqkv_MB, lora_mem, NMEM, QKVO, RANK, nullptr);
    scatter_add_rows<<<dim3(QKVO / 256, NIM), 256>>>(qkv, lora_im, imidx, QKVO);
    scatter_add_rows<<<dim3(QKVO / 256, NMEM), 256>>>(qkv, lora_mem, memidx, QKVO);

    // ---- KV cache (copy inputs, fill 128 slots from raw k/v with beacon RoPE) ----
    cudaMemcpyAsync(kc_out, kc_in, (size_t)CACHE_ELEMS * sizeof(float), cudaMemcpyDeviceToDevice);
    cudaMemcpyAsync(vc_out, vc_in, (size_t)CACHE_ELEMS * sizeof(float), cudaMemcpyDeviceToDevice);
    fill_cache_kernel<<<NMEM, dim3(64, 8)>>>(qkv, memidx, blkoff, bcos, bsin, kc_out, vc_out);

    // ---- RoPE on q,k (in place; AFTER cache fill which needs raw k) ----
    rope_qk_kernel<<<dim3(TT, NHEADS + NKVH), 64>>>(qkv, cosp, sinp);

    // ---- Causal flash attention ----
    cudaFuncSetAttribute(flash_attn_kernel, cudaFuncAttributeMaxDynamicSharedMemorySize, FA_SMEM);
    flash_attn_kernel<<<dim3(TT / 64, NHEADS), 256, FA_SMEM>>>(qkv, attn);

    // ---- Output projection + PLoRA (writes directly into d_out) ----
    sgemm_bt<<<dim3(HID / 128, TT / 128), 256>>>(attn, wo_w, outp, TT, HID, HID, nullptr);
    sgemm_bt<<<dim3(RANK / 128, NIM / 128), 256>>>(attn, wo_A, tmp_im, NIM, RANK, HID, imidx);
    sgemm_bt<<<dim3(RANK / 128, NMEM / 128), 256>>>(attn, wo_MA, tmp_mem, NMEM, RANK, HID, memidx);
    sgemm_bt<<<dim3(HID / 128, NIM / 128), 256>>>(tmp_im, wo_B, lora_im, NIM, HID, RANK, nullptr);
    sgemm_bt<<<dim3(HID / 128, NMEM / 128), 256>>>(tmp_mem, wo_MB, lora_mem, NMEM, HID, RANK, nullptr);
    scatter_add_rows<<<dim3(HID / 256, NIM), 256>>>(outp, lora_im, imidx, HID);
    scatter_add_rows<<<dim3(HID / 256, NMEM), 256>>>(outp, lora_mem, memidx, HID);
}

// round 2
// speedup vs baseline: 1.7294x; 1.7294x over previous
#include <cuda_runtime.h>
#include <cuda_bf16.h>
#include <math.h>
#include <float.h>
#include <stdint.h>

// ---------------- problem constants ----------------
#define TT     2048
#define HID    4096
#define NHEADS 32
#define NKVH   8
#define HDIM   128
#define QKVO   6144          // (32 + 2*8) * 128
#define RANK   256
#define NIM    512
#define NMEM   128
#define CACHE_ELEMS (4*64*NKVH*HDIM)   // 262144

// ---------------- scratch (device globals; no allocs allowed) ----------------
__device__ float g_qkv[TT * QKVO];        // 50.3 MB
__device__ float g_attn[TT * HID];        // 33.5 MB
__device__ float g_tmp_im[NIM * RANK];
__device__ float g_tmp_mem[NMEM * RANK];
__device__ float g_lora_im[NIM * QKVO];
__device__ float g_lora_mem[NMEM * QKVO];

// =====================================================================
// Tensor-core GEMM with bf16 hi/lo split (error-compensated):
//   C[m,n] = sum_k A[row(m),k] * B[n,k]   (A row-major, B n-major k-contig)
// acc += Ahi*Bhi + Ahi*Blo + Alo*Bhi  (fp32 accumulate) — rel err ~2^-18.
// BM=BN=128, BK=32, 256 threads (8 warps = 2m x 4n), warp tile 64x32,
// per warp 4x4 m16n8k16 mma tiles.
// Requires M%128==0, N%128==0, K%32==0.
// =====================================================================
#define LDKS 40   // smem row stride in bf16 elements (conflict-free)

__device__ __forceinline__ uint32_t pack_bf16(float x, float y) {
    __nv_bfloat162 t = __floats2bfloat162_rn(x, y);
    return *reinterpret_cast<uint32_t*>(&t);
}

__device__ __forceinline__ void mma16816(float* c, const uint32_t* a, const uint32_t* b) {
    asm volatile(
        "mma.sync.aligned.m16n8k16.row.col.f32.bf16.bf16.f32 "
        "{%0,%1,%2,%3}, {%4,%5,%6,%7}, {%8,%9}, {%0,%1,%2,%3};\n"
        : "+f"(c[0]), "+f"(c[1]), "+f"(c[2]), "+f"(c[3])
        : "r"(a[0]), "r"(a[1]), "r"(a[2]), "r"(a[3]), "r"(b[0]), "r"(b[1]));
}

__global__ __launch_bounds__(256) void gemm_bf16s(
    const float* __restrict__ A, const float* __restrict__ B,
    float* __restrict__ C, int M, int N, int K,
    const int* __restrict__ gatherA)
{
    __shared__ __nv_bfloat16 Ah[128 * LDKS];
    __shared__ __nv_bfloat16 Al[128 * LDKS];
    __shared__ __nv_bfloat16 Bh[128 * LDKS];
    __shared__ __nv_bfloat16 Bl[128 * LDKS];

    int tid = threadIdx.x;
    int bm = blockIdx.y, bn = blockIdx.x;
    int warp = tid >> 5, lane = tid & 31;
    int wm = warp & 1, wn = warp >> 1;          // 2 x 4 warp grid
    int gid = lane >> 2, tig = lane & 3;

    // global load assignments: 128 rows x 8 float4 per operand, 4 per thread
    const float* aptr[4];
    const float* bptr[4];
    int soff[4];
#pragma unroll
    for (int i = 0; i < 4; i++) {
        int idx = tid + 256 * i;
        int r = idx >> 3;
        int c = (idx & 7) * 4;
        int ar = bm * 128 + r;
        if (gatherA) ar = __ldg(&gatherA[ar]);
        aptr[i] = A + (size_t)ar * K + c;
        bptr[i] = B + (size_t)(bn * 128 + r) * K + c;
        soff[i] = r * LDKS + c;
    }

    float acc[4][4][4];
#pragma unroll
    for (int mt = 0; mt < 4; mt++)
#pragma unroll
        for (int nt = 0; nt < 4; nt++)
#pragma unroll
            for (int e = 0; e < 4; e++) acc[mt][nt][e] = 0.f;

    for (int k0 = 0; k0 < K; k0 += 32) {
        float4 av[4], bv[4];
#pragma unroll
        for (int i = 0; i < 4; i++) {
            av[i] = *(const float4*)(aptr[i] + k0);
            bv[i] = *(const float4*)(bptr[i] + k0);
        }
        __syncthreads();   // protect previous iteration's fragment reads
#pragma unroll
        for (int i = 0; i < 4; i++) {
            float4 v = av[i];
            float hx = __bfloat162float(__float2bfloat16(v.x));
            float hy = __bfloat162float(__float2bfloat16(v.y));
            float hz = __bfloat162float(__float2bfloat16(v.z));
            float hw = __bfloat162float(__float2bfloat16(v.w));
            *(uint32_t*)&Ah[soff[i]]     = pack_bf16(hx, hy);
            *(uint32_t*)&Ah[soff[i] + 2] = pack_bf16(hz, hw);
            *(uint32_t*)&Al[soff[i]]     = pack_bf16(v.x - hx, v.y - hy);
            *(uint32_t*)&Al[soff[i] + 2] = pack_bf16(v.z - hz, v.w - hw);
            v = bv[i];
            hx = __bfloat162float(__float2bfloat16(v.x));
            hy = __bfloat162float(__float2bfloat16(v.y));
            hz = __bfloat162float(__float2bfloat16(v.z));
            hw = __bfloat162float(__float2bfloat16(v.w));
            *(uint32_t*)&Bh[soff[i]]     = pack_bf16(hx, hy);
            *(uint32_t*)&Bh[soff[i] + 2] = pack_bf16(hz, hw);
            *(uint32_t*)&Bl[soff[i]]     = pack_bf16(v.x - hx, v.y - hy);
            *(uint32_t*)&Bl[soff[i] + 2] = pack_bf16(v.z - hz, v.w - hw);
        }
        __syncthreads();

#pragma unroll
        for (int ks = 0; ks < 32; ks += 16) {
            uint32_t ah[4][4], al[4][4];
#pragma unroll
            for (int mt = 0; mt < 4; mt++) {
                int base = (wm * 64 + mt * 16 + gid) * LDKS + ks + tig * 2;
                ah[mt][0] = *(const uint32_t*)&Ah[base];
                ah[mt][1] = *(const uint32_t*)&Ah[base + 8 * LDKS];
                ah[mt][2] = *(const uint32_t*)&Ah[base + 8];
                ah[mt][3] = *(const uint32_t*)&Ah[base + 8 * LDKS + 8];
                al[mt][0] = *(const uint32_t*)&Al[base];
                al[mt][1] = *(const uint32_t*)&Al[base + 8 * LDKS];
                al[mt][2] = *(const uint32_t*)&Al[base + 8];
                al[mt][3] = *(const uint32_t*)&Al[base + 8 * LDKS + 8];
            }
#pragma unroll
            for (int nt = 0; nt < 4; nt++) {
                int basen = (wn * 32 + nt * 8 + gid) * LDKS + ks + tig * 2;
                uint32_t bh[2], bl[2];
                bh[0] = *(const uint32_t*)&Bh[basen];
                bh[1] = *(const uint32_t*)&Bh[basen + 8];
                bl[0] = *(const uint32_t*)&Bl[basen];
                bl[1] = *(const uint32_t*)&Bl[basen + 8];
#pragma unroll
                for (int mt = 0; mt < 4; mt++) {
                    mma16816(acc[mt][nt], ah[mt], bh);
                    mma16816(acc[mt][nt], ah[mt], bl);
                    mma16816(acc[mt][nt], al[mt], bh);
                }
            }
        }
    }

    // epilogue
#pragma unroll
    for (int mt = 0; mt < 4; mt++) {
        int r0 = bm * 128 + wm * 64 + mt * 16 + gid;
#pragma unroll
        for (int nt = 0; nt < 4; nt++) {
            int c0 = bn * 128 + wn * 32 + nt * 8 + tig * 2;
            *(float2*)&C[(size_t)r0 * N + c0] =
                make_float2(acc[mt][nt][0], acc[mt][nt][1]);
            *(float2*)&C[(size_t)(r0 + 8) * N + c0] =
                make_float2(acc[mt][nt][2], acc[mt][nt][3]);
        }
    }
}

// =====================================================================
// Scatter-add: C[idx[row], :] += L[row, :]   (atomic: duplicates accumulate)
// =====================================================================
__global__ void scatter_add_rows(float* __restrict__ C, const float* __restrict__ L,
                                 const int* __restrict__ idx, int N)
{
    int row = blockIdx.y;
    int col = blockIdx.x * 256 + threadIdx.x;
    int r = idx[row];
    atomicAdd(&C[(size_t)r * N + col], L[(size_t)row * N + col]);
}

// =====================================================================
// RoPE in place on q and k inside the qkv buffer. grid (T, 40), 64 threads.
// =====================================================================
__global__ void rope_qk_kernel(float* __restrict__ qkv,
                               const float* __restrict__ cosp,
                               const float* __restrict__ sinp)
{
    int t = blockIdx.x, h = blockIdx.y, d = threadIdx.x; // d < 64
    const float* c = cosp + (size_t)t * HDIM;
    const float* s = sinp + (size_t)t * HDIM;
    float* base;
    if (h < NHEADS) base = qkv + (size_t)t * QKVO + (size_t)((h >> 2) * 6 + (h & 3)) * HDIM;
    else            base = qkv + (size_t)t * QKVO + (size_t)((h - NHEADS) * 6 + 4) * HDIM;
    float x1 = base[d], x2 = base[d + 64];
    base[d]      = x1 * c[d]      - x2 * s[d];
    base[d + 64] = x2 * c[d + 64] + x1 * s[d + 64];
}

// =====================================================================
// KV-cache fill from RAW (pre-RoPE) k/v, with beacon RoPE on k.
// =====================================================================
__global__ void fill_cache_kernel(const float* __restrict__ qkv,
                                  const int* __restrict__ mem_idx,
                                  const int* __restrict__ blkoff,
                                  const float* __restrict__ bcos,
                                  const float* __restrict__ bsin,
                                  float* __restrict__ kc, float* __restrict__ vc)
{
    int m = blockIdx.x;          // 0..127
    int h = threadIdx.y;         // 0..7
    int d = threadIdx.x;         // 0..63
    int tok = mem_idx[m];
    int blk = blkoff[m >> 6];
    int off = m & 63;
    const float* kb = qkv + (size_t)tok * QKVO + (size_t)(h * 6 + 4) * HDIM;
    const float* vb = qkv + (size_t)tok * QKVO + (size_t)(h * 6 + 5) * HDIM;
    size_t dsti = (((size_t)(blk * 64 + off)) * NKVH + h) * HDIM;
    const float* c = bcos + (size_t)m * HDIM;
    const float* s = bsin + (size_t)m * HDIM;
    float x1 = kb[d], x2 = kb[d + 64];
    kc[dsti + d]      = x1 * c[d]      - x2 * s[d];
    kc[dsti + d + 64] = x2 * c[d + 64] + x1 * s[d + 64];
    vc[dsti + d]      = vb[d];
    vc[dsti + d + 64] = vb[d + 64];
}

// =====================================================================
// Flash attention (fp32), causal, GQA 4:1.
// grid (T/64 q-blocks, 32 heads), 256 threads, dynamic smem ~117 KB.
// =====================================================================
#define FA_SMEM ((3 * 64 * 132 + 64 * 68 + 3 * 64) * 4)

__global__ __launch_bounds__(256) void flash_attn_kernel(
    const float* __restrict__ qkv, float* __restrict__ outp)
{
    extern __shared__ float sm[];
    float* Qs    = sm;                       // 64 x 132
    float* Ks    = Qs + 64 * 132;
    float* Vs    = Ks + 64 * 132;
    float* Ps    = Vs + 64 * 132;            // 64 x 68
    float* m_run = Ps + 64 * 68;             // 64
    float* l_run = m_run + 64;
    float* fac   = l_run + 64;

    int tid = threadIdx.x;
    int qb = blockIdx.x, h = blockIdx.y;
    int kv = h >> 2, g = h & 3;
    int qoff = (kv * 6 + g) * HDIM;
    int koff = (kv * 6 + 4) * HDIM;
    int voff = (kv * 6 + 5) * HDIM;

#pragma unroll
    for (int ii = 0; ii < 8; ii++) {
        int idx = tid + 256 * ii;
        int r = idx >> 5, c4 = (idx & 31) << 2;
        float4 v = *(const float4*)(qkv + (size_t)(qb * 64 + r) * QKVO + qoff + c4);
        *(float4*)&Qs[r * 132 + c4] = v;
    }
    if (tid < 64) { m_run[tid] = -FLT_MAX; l_run[tid] = 0.f; }
    float O[32];
#pragma unroll
    for (int i = 0; i < 32; i++) O[i] = 0.f;
    __syncthreads();

    int rg   = tid >> 4;    // S-phase row group (4 rows)
    int lk16 = tid & 15;    // lane within row group
    int qi_o = tid >> 2;    // O-phase row
    int q4   = tid & 3;

    const float scale = 0.08838834764831845f; // 1/sqrt(128)

    for (int kb = 0; kb <= qb; kb++) {
#pragma unroll
        for (int ii = 0; ii < 8; ii++) {
            int idx = tid + 256 * ii;
            int r = idx >> 5, c4 = (idx & 31) << 2;
            const float* src = qkv + (size_t)(kb * 64 + r) * QKVO;
            *(float4*)&Ks[r * 132 + c4] = *(const float4*)(src + koff + c4);
            *(float4*)&Vs[r * 132 + c4] = *(const float4*)(src + voff + c4);
        }
        __syncthreads();

        float S[4][4];
#pragma unroll
        for (int i = 0; i < 4; i++)
#pragma unroll
            for (int j = 0; j < 4; j++) S[i][j] = 0.f;

#pragma unroll 4
        for (int d4 = 0; d4 < 32; d4++) {
            float4 qv[4], kk4[4];
#pragma unroll
            for (int i = 0; i < 4; i++)
                qv[i] = *(const float4*)&Qs[(rg * 4 + i) * 132 + d4 * 4];
#pragma unroll
            for (int j = 0; j < 4; j++)
                kk4[j] = *(const float4*)&Ks[(lk16 + 16 * j) * 132 + d4 * 4];
#pragma unroll
            for (int i = 0; i < 4; i++)
#pragma unroll
                for (int j = 0; j < 4; j++)
                    S[i][j] += qv[i].x * kk4[j].x + qv[i].y * kk4[j].y
                             + qv[i].z * kk4[j].z + qv[i].w * kk4[j].w;
        }

        int qg0 = qb * 64 + rg * 4;
        int kg0 = kb * 64 + lk16;
        float rmax[4];
#pragma unroll
        for (int i = 0; i < 4; i++) {
            rmax[i] = -FLT_MAX;
#pragma unroll
            for (int j = 0; j < 4; j++) {
                int kg = kg0 + 16 * j;
                S[i][j] = (kg <= qg0 + i) ? S[i][j] * scale : -FLT_MAX;
                rmax[i] = fmaxf(rmax[i], S[i][j]);
            }
        }
#pragma unroll
        for (int mm = 1; mm < 16; mm <<= 1)
#pragma unroll
            for (int i = 0; i < 4; i++)
                rmax[i] = fmaxf(rmax[i], __shfl_xor_sync(0xffffffffu, rmax[i], mm));

        if (lk16 == 0) {
#pragma unroll
            for (int i = 0; i < 4; i++) {
                int qi = rg * 4 + i;
                float mo = m_run[qi];
                float mn = fmaxf(mo, rmax[i]);
                m_run[qi] = mn;
                fac[qi] = __expf(mo - mn);
            }
        }
        __syncwarp();

        float rsum[4];
#pragma unroll
        for (int i = 0; i < 4; i++) {
            float mn = m_run[rg * 4 + i];
            rsum[i] = 0.f;
#pragma unroll
            for (int j = 0; j < 4; j++) {
                float p = __expf(S[i][j] - mn);
                rsum[i] += p;
                Ps[(rg * 4 + i) * 68 + lk16 + 16 * j] = p;
            }
        }
#pragma unroll
        for (int mm = 1; mm < 16; mm <<= 1)
#pragma unroll
            for (int i = 0; i < 4; i++)
                rsum[i] += __shfl_xor_sync(0xffffffffu, rsum[i], mm);
        if (lk16 == 0) {
#pragma unroll
            for (int i = 0; i < 4; i++) {
                int qi = rg * 4 + i;
                l_run[qi] = l_run[qi] * fac[qi] + rsum[i];
            }
        }
        __syncthreads();

        // O phase
        float f = fac[qi_o];
#pragma unroll
        for (int i = 0; i < 32; i++) O[i] *= f;
#pragma unroll 8
        for (int j = 0; j < 64; j++) {
            float p = Ps[qi_o * 68 + j];
#pragma unroll
            for (int cc = 0; cc < 8; cc++) {
                float4 vv = *(const float4*)&Vs[j * 132 + q4 * 4 + 16 * cc];
                O[cc * 4 + 0] = fmaf(p, vv.x, O[cc * 4 + 0]);
                O[cc * 4 + 1] = fmaf(p, vv.y, O[cc * 4 + 1]);
                O[cc * 4 + 2] = fmaf(p, vv.z, O[cc * 4 + 2]);
                O[cc * 4 + 3] = fmaf(p, vv.w, O[cc * 4 + 3]);
            }
        }
        __syncthreads();
    }

    float inv = 1.f / l_run[qi_o];
    size_t obase = (size_t)(qb * 64 + qi_o) * HID + (size_t)h * HDIM;
#pragma unroll
    for (int cc = 0; cc < 8; cc++) {
        float4 vv = make_float4(O[cc * 4 + 0] * inv, O[cc * 4 + 1] * inv,
                                O[cc * 4 + 2] * inv, O[cc * 4 + 3] * inv);
        *(float4*)&outp[obase + q4 * 4 + 16 * cc] = vv;
    }
}

// =====================================================================
// Host orchestration
// =====================================================================
extern "C" void kernel_launch(void* const* d_in, const int* in_sizes, int n_in,
                              void* d_out, int out_size)
{
    const float* hs     = (const float*)d_in[0];
    const float* cosp   = (const float*)d_in[1];
    const float* sinp   = (const float*)d_in[2];
    const float* bcos   = (const float*)d_in[3];
    const float* bsin   = (const float*)d_in[4];
    const int*   memidx = (const int*)d_in[5];
    const int*   imidx  = (const int*)d_in[6];
    const float* kc_in  = (const float*)d_in[7];
    const float* vc_in  = (const float*)d_in[8];
    const int*   blkoff = (const int*)d_in[9];
    const float* wqkv_w = (const float*)d_in[10];
    const float* wqkv_A = (const float*)d_in[11];
    const float* wqkv_B = (const float*)d_in[12];
    const float* wqkv_MA= (const float*)d_in[13];
    const float* wqkv_MB= (const float*)d_in[14];
    const float* wo_w   = (const float*)d_in[15];
    const float* wo_A   = (const float*)d_in[16];
    const float* wo_B   = (const float*)d_in[17];
    const float* wo_MA  = (const float*)d_in[18];
    const float* wo_MB  = (const float*)d_in[19];

    float* outp   = (float*)d_out;
    float* kc_out = outp + (size_t)TT * HID;
    float* vc_out = kc_out + CACHE_ELEMS;

    float *qkv, *attn, *tmp_im, *tmp_mem, *lora_im, *lora_mem;
    cudaGetSymbolAddress((void**)&qkv,      g_qkv);
    cudaGetSymbolAddress((void**)&attn,     g_attn);
    cudaGetSymbolAddress((void**)&tmp_im,   g_tmp_im);
    cudaGetSymbolAddress((void**)&tmp_mem,  g_tmp_mem);
    cudaGetSymbolAddress((void**)&lora_im,  g_lora_im);
    cudaGetSymbolAddress((void**)&lora_mem, g_lora_mem);

    // ---- QKV projection + PLoRA ----
    gemm_bf16s<<<dim3(QKVO / 128, TT / 128), 256>>>(hs, wqkv_w, qkv, TT, QKVO, HID, nullptr);
    gemm_bf16s<<<dim3(RANK / 128, NIM / 128), 256>>>(hs, wqkv_A, tmp_im, NIM, RANK, HID, imidx);
    gemm_bf16s<<<dim3(RANK / 128, NMEM / 128), 256>>>(hs, wqkv_MA, tmp_mem, NMEM, RANK, HID, memidx);
    gemm_bf16s<<<dim3(QKVO / 128, NIM / 128), 256>>>(tmp_im, wqkv_B, lora_im, NIM, QKVO, RANK, nullptr);
    gemm_bf16s<<<dim3(QKVO / 128, NMEM / 128), 256>>>(tmp_mem, wqkv_MB, lora_mem, NMEM, QKVO, RANK, nullptr);
    scatter_add_rows<<<dim3(QKVO / 256, NIM), 256>>>(qkv, lora_im, imidx, QKVO);
    scatter_add_rows<<<dim3(QKVO / 256, NMEM), 256>>>(qkv, lora_mem, memidx, QKVO);

    // ---- KV cache (copy inputs, fill 128 slots from raw k/v with beacon RoPE) ----
    cudaMemcpyAsync(kc_out, kc_in, (size_t)CACHE_ELEMS * sizeof(float), cudaMemcpyDeviceToDevice);
    cudaMemcpyAsync(vc_out, vc_in, (size_t)CACHE_ELEMS * sizeof(float), cudaMemcpyDeviceToDevice);
    fill_cache_kernel<<<NMEM, dim3(64, 8)>>>(qkv, memidx, blkoff, bcos, bsin, kc_out, vc_out);

    // ---- RoPE on q,k (in place; AFTER cache fill which needs raw k) ----
    rope_qk_kernel<<<dim3(TT, NHEADS + NKVH), 64>>>(qkv, cosp, sinp);

    // ---- Causal flash attention ----
    cudaFuncSetAttribute(flash_attn_kernel, cudaFuncAttributeMaxDynamicSharedMemorySize, FA_SMEM);
    flash_attn_kernel<<<dim3(TT / 64, NHEADS), 256, FA_SMEM>>>(qkv, attn);

    // ---- Output projection + PLoRA (writes directly into d_out) ----
    gemm_bf16s<<<dim3(HID / 128, TT / 128), 256>>>(attn, wo_w, outp, TT, HID, HID, nullptr);
    gemm_bf16s<<<dim3(RANK / 128, NIM / 128), 256>>>(attn, wo_A, tmp_im, NIM, RANK, HID, imidx);
    gemm_bf16s<<<dim3(RANK / 128, NMEM / 128), 256>>>(attn, wo_MA, tmp_mem, NMEM, RANK, HID, memidx);
    gemm_bf16s<<<dim3(HID / 128, NIM / 128), 256>>>(tmp_im, wo_B, lora_im, NIM, HID, RANK, nullptr);
    gemm_bf16s<<<dim3(HID / 128, NMEM / 128), 256>>>(tmp_mem, wo_MB, lora_mem, NMEM, HID, RANK, nullptr);
    scatter_add_rows<<<dim3(HID / 256, NIM), 256>>>(outp, lora_im, imidx, HID);
    scatter_add_rows<<<dim3(HID / 256, NMEM), 256>>>(outp, lora_mem, memidx, HID);
}